// round 1
// baseline (speedup 1.0000x reference)
#include <cuda_runtime.h>

// ---------------------------------------------------------------------------
// MultiHeadAttention: B=2, S=2048, D_MODEL=1024, H=16, DEPTH=64
// Output buffer layout (reference returns (out, attn)):
//   d_out[0 .. B*S*D)              : out  (B,S,D) fp32
//   d_out[B*S*D .. +B*H*S*S)       : attn (B,H,S,S) fp32
// ---------------------------------------------------------------------------

namespace {
constexpr int Bc = 2;
constexpr int Sc = 2048;
constexpr int DM = 1024;
constexpr int Hc = 16;
constexpr int DEPTH = 64;
constexpr int BH = Bc * Hc;        // 32
constexpr int MROWS = Bc * Sc;     // 4096
constexpr float SCALE = 0.125f;    // 1/sqrt(DEPTH)
constexpr float NEG_BIG = -3.0e38f;
}

// Scratch (allocation-free rule: __device__ globals)
__device__ float g_qh[BH * Sc * DEPTH];   // (B,H,S,depth)
__device__ float g_kh[BH * Sc * DEPTH];
__device__ float g_vh[BH * Sc * DEPTH];
__device__ float g_ctx[BH * Sc * DEPTH];  // attention context, head layout
__device__ float g_m[BH * Sc];            // per-row softmax max
__device__ float g_s[BH * Sc];            // per-row softmax sum

__device__ __forceinline__ float rmax16(float v) {
#pragma unroll
    for (int o = 8; o > 0; o >>= 1)
        v = fmaxf(v, __shfl_xor_sync(0xffffffffu, v, o));
    return v;
}
__device__ __forceinline__ float rsum16(float v) {
#pragma unroll
    for (int o = 8; o > 0; o >>= 1)
        v += __shfl_xor_sync(0xffffffffu, v, o);
    return v;
}

// ---------------------------------------------------------------------------
// QKV projection: C = X @ W + bias, written in head-split layout
// Tiles: 128(M) x 64(N) x 16(K), 256 threads, 8x4 per thread.
// ---------------------------------------------------------------------------
__global__ void proj_heads_kernel(const float* __restrict__ X,
                                  const float* __restrict__ W,
                                  const float* __restrict__ bias,
                                  int sel) {
    float* out = (sel == 0) ? g_qh : ((sel == 1) ? g_kh : g_vh);
    __shared__ float As[16][132];  // [k][m], padded
    __shared__ float Bs[16][64];   // [k][n]
    const int tid = threadIdx.x;
    const int tx = tid & 15;   // N dir, 4 cols each
    const int ty = tid >> 4;   // M dir, 8 rows each
    const int m0 = blockIdx.y * 128;
    const int n0 = blockIdx.x * 64;

    float acc[8][4];
#pragma unroll
    for (int i = 0; i < 8; i++)
#pragma unroll
        for (int j = 0; j < 4; j++) acc[i][j] = 0.0f;

    for (int k0 = 0; k0 < DM; k0 += 16) {
#pragma unroll
        for (int i = 0; i < 8; i++) {
            int e = tid + i * 256;
            int r = e >> 4, c = e & 15;
            As[c][r] = X[(size_t)(m0 + r) * DM + k0 + c];
        }
#pragma unroll
        for (int i = 0; i < 4; i++) {
            int e = tid + i * 256;
            int r = e >> 6, c = e & 63;
            Bs[r][c] = W[(size_t)(k0 + r) * DM + n0 + c];
        }
        __syncthreads();
#pragma unroll
        for (int kk = 0; kk < 16; kk++) {
            float a[8], bv[4];
#pragma unroll
            for (int i = 0; i < 8; i++) a[i] = As[kk][ty * 8 + i];
#pragma unroll
            for (int j = 0; j < 4; j++) bv[j] = Bs[kk][tx * 4 + j];
#pragma unroll
            for (int i = 0; i < 8; i++)
#pragma unroll
                for (int j = 0; j < 4; j++)
                    acc[i][j] = fmaf(a[i], bv[j], acc[i][j]);
        }
        __syncthreads();
    }

#pragma unroll
    for (int i = 0; i < 8; i++) {
        int row = m0 + ty * 8 + i;
        int b = row / Sc, s = row % Sc;
#pragma unroll
        for (int j = 0; j < 4; j++) {
            int col = n0 + tx * 4 + j;
            int h = col >> 6, d = col & 63;
            out[(((size_t)(b * Hc + h)) * Sc + s) * DEPTH + d] =
                acc[i][j] + bias[col];
        }
    }
}

// ---------------------------------------------------------------------------
// Pass 1: logits = Q @ K^T * SCALE (raw, written to attn region) + online
// per-row (max, sumexp). One block = one (bh, 64-row q tile) over all 2048 k.
// ---------------------------------------------------------------------------
__global__ void attn_logits_kernel(float* __restrict__ attn) {
    const int bh = blockIdx.y;
    const int q0 = blockIdx.x * 64;
    __shared__ float Qs[64][65];
    __shared__ float Ks[64][65];
    const int tid = threadIdx.x;
    const int tx = tid & 15, ty = tid >> 4;

    const float* Qb = g_qh + (size_t)bh * Sc * DEPTH;
    const float* Kb = g_kh + (size_t)bh * Sc * DEPTH;

#pragma unroll
    for (int i = 0; i < 16; i++) {
        int e = tid + i * 256;
        int r = e >> 6, c = e & 63;
        Qs[r][c] = Qb[(size_t)(q0 + r) * DEPTH + c];
    }

    float m_run[4], s_run[4];
#pragma unroll
    for (int i = 0; i < 4; i++) { m_run[i] = NEG_BIG; s_run[i] = 0.0f; }

    for (int k0 = 0; k0 < Sc; k0 += 64) {
        __syncthreads();
#pragma unroll
        for (int i = 0; i < 16; i++) {
            int e = tid + i * 256;
            int r = e >> 6, c = e & 63;
            Ks[r][c] = Kb[(size_t)(k0 + r) * DEPTH + c];
        }
        __syncthreads();

        float l[4][4];
#pragma unroll
        for (int i = 0; i < 4; i++)
#pragma unroll
            for (int j = 0; j < 4; j++) l[i][j] = 0.0f;

#pragma unroll
        for (int d = 0; d < 64; d++) {
            float a[4], bv[4];
#pragma unroll
            for (int i = 0; i < 4; i++) a[i] = Qs[ty * 4 + i][d];
#pragma unroll
            for (int j = 0; j < 4; j++) bv[j] = Ks[tx * 4 + j][d];
#pragma unroll
            for (int i = 0; i < 4; i++)
#pragma unroll
                for (int j = 0; j < 4; j++)
                    l[i][j] = fmaf(a[i], bv[j], l[i][j]);
        }

#pragma unroll
        for (int i = 0; i < 4; i++) {
            int row = q0 + ty * 4 + i;
            float* arow = attn + ((size_t)(bh * Sc + row)) * Sc + k0 + tx * 4;
            float tmax = NEG_BIG;
#pragma unroll
            for (int j = 0; j < 4; j++) {
                l[i][j] *= SCALE;
                arow[j] = l[i][j];
                tmax = fmaxf(tmax, l[i][j]);
            }
            tmax = rmax16(tmax);
            float mnew = fmaxf(m_run[i], tmax);
            float ps = 0.0f;
#pragma unroll
            for (int j = 0; j < 4; j++) ps += expf(l[i][j] - mnew);
            ps = rsum16(ps);
            s_run[i] = s_run[i] * expf(m_run[i] - mnew) + ps;
            m_run[i] = mnew;
        }
    }

    if (tx == 0) {
#pragma unroll
        for (int i = 0; i < 4; i++) {
            int row = q0 + ty * 4 + i;
            g_m[bh * Sc + row] = m_run[i];
            g_s[bh * Sc + row] = s_run[i];
        }
    }
}

// ---------------------------------------------------------------------------
// Pass 2: normalize attn in place (final output) and ctx = attn @ V.
// ---------------------------------------------------------------------------
__global__ void attn_av_kernel(float* __restrict__ attn) {
    const int bh = blockIdx.y;
    const int q0 = blockIdx.x * 64;
    __shared__ float Ps[64][65];  // [q][k]
    __shared__ float Vs[64][65];  // [k][d]
    const int tid = threadIdx.x;
    const int tx = tid & 15, ty = tid >> 4;

    const float* Vb = g_vh + (size_t)bh * Sc * DEPTH;

    float mrow[4], sinv[4];
#pragma unroll
    for (int i = 0; i < 4; i++) {
        int row = q0 + ty * 4 + i;
        mrow[i] = g_m[bh * Sc + row];
        sinv[i] = 1.0f / g_s[bh * Sc + row];
    }

    float acc[4][4];
#pragma unroll
    for (int i = 0; i < 4; i++)
#pragma unroll
        for (int j = 0; j < 4; j++) acc[i][j] = 0.0f;

    for (int k0 = 0; k0 < Sc; k0 += 64) {
        __syncthreads();
#pragma unroll
        for (int i = 0; i < 16; i++) {
            int e = tid + i * 256;
            int r = e >> 6, c = e & 63;
            Vs[r][c] = Vb[(size_t)(k0 + r) * DEPTH + c];
        }
#pragma unroll
        for (int i = 0; i < 4; i++) {
            int row = q0 + ty * 4 + i;
            float* arow = attn + ((size_t)(bh * Sc + row)) * Sc + k0 + tx * 4;
#pragma unroll
            for (int j = 0; j < 4; j++) {
                float p = expf(arow[j] - mrow[i]) * sinv[i];
                arow[j] = p;                       // final normalized attn
                Ps[ty * 4 + i][tx * 4 + j] = p;
            }
        }
        __syncthreads();
#pragma unroll
        for (int kk = 0; kk < 64; kk++) {
            float a[4], bv[4];
#pragma unroll
            for (int i = 0; i < 4; i++) a[i] = Ps[ty * 4 + i][kk];
#pragma unroll
            for (int j = 0; j < 4; j++) bv[j] = Vs[kk][tx * 4 + j];
#pragma unroll
            for (int i = 0; i < 4; i++)
#pragma unroll
                for (int j = 0; j < 4; j++)
                    acc[i][j] = fmaf(a[i], bv[j], acc[i][j]);
        }
    }

    float* Cb = g_ctx + (size_t)bh * Sc * DEPTH;
#pragma unroll
    for (int i = 0; i < 4; i++)
#pragma unroll
        for (int j = 0; j < 4; j++)
            Cb[(size_t)(q0 + ty * 4 + i) * DEPTH + tx * 4 + j] = acc[i][j];
}

// ---------------------------------------------------------------------------
// Output projection: out = ctx(merged heads) @ wo + bo.
// Same tiling as proj_heads; A is read from head layout via index mapping.
// ---------------------------------------------------------------------------
__global__ void out_proj_kernel(const float* __restrict__ WO,
                                const float* __restrict__ bo,
                                float* __restrict__ out) {
    __shared__ float As[16][132];
    __shared__ float Bs[16][64];
    const int tid = threadIdx.x;
    const int tx = tid & 15, ty = tid >> 4;
    const int m0 = blockIdx.y * 128;
    const int n0 = blockIdx.x * 64;

    float acc[8][4];
#pragma unroll
    for (int i = 0; i < 8; i++)
#pragma unroll
        for (int j = 0; j < 4; j++) acc[i][j] = 0.0f;

    for (int k0 = 0; k0 < DM; k0 += 16) {
        const int h = k0 >> 6;
        const int dbase = k0 & 63;
#pragma unroll
        for (int i = 0; i < 8; i++) {
            int e = tid + i * 256;
            int r = e >> 4, c = e & 15;
            int row = m0 + r;
            int b = row / Sc, s = row % Sc;
            As[c][r] = g_ctx[(((size_t)(b * Hc + h)) * Sc + s) * DEPTH + dbase + c];
        }
#pragma unroll
        for (int i = 0; i < 4; i++) {
            int e = tid + i * 256;
            int r = e >> 6, c = e & 63;
            Bs[r][c] = WO[(size_t)(k0 + r) * DM + n0 + c];
        }
        __syncthreads();
#pragma unroll
        for (int kk = 0; kk < 16; kk++) {
            float a[8], bv[4];
#pragma unroll
            for (int i = 0; i < 8; i++) a[i] = As[kk][ty * 8 + i];
#pragma unroll
            for (int j = 0; j < 4; j++) bv[j] = Bs[kk][tx * 4 + j];
#pragma unroll
            for (int i = 0; i < 8; i++)
#pragma unroll
                for (int j = 0; j < 4; j++)
                    acc[i][j] = fmaf(a[i], bv[j], acc[i][j]);
        }
        __syncthreads();
    }

#pragma unroll
    for (int i = 0; i < 8; i++) {
        int row = m0 + ty * 8 + i;
#pragma unroll
        for (int j = 0; j < 4; j++) {
            int col = n0 + tx * 4 + j;
            out[(size_t)row * DM + col] = acc[i][j] + bo[col];
        }
    }
}

// ---------------------------------------------------------------------------
// Launch
// ---------------------------------------------------------------------------
extern "C" void kernel_launch(void* const* d_in, const int* in_sizes, int n_in,
                              void* d_out, int out_size) {
    // metadata order: v, k, q, wq, bq, wk, bk, wv, bv, wo, bo
    const float* v  = (const float*)d_in[0];
    const float* k  = (const float*)d_in[1];
    const float* q  = (const float*)d_in[2];
    const float* wq = (const float*)d_in[3];
    const float* bq = (const float*)d_in[4];
    const float* wk = (const float*)d_in[5];
    const float* bk = (const float*)d_in[6];
    const float* wv = (const float*)d_in[7];
    const float* bv = (const float*)d_in[8];
    const float* wo = (const float*)d_in[9];
    const float* bo = (const float*)d_in[10];

    float* out  = (float*)d_out;
    float* attn = out + (size_t)Bc * Sc * DM;  // second tuple element

    dim3 gproj(DM / 64, MROWS / 128);          // (16, 32)
    proj_heads_kernel<<<gproj, 256>>>(q, wq, bq, 0);
    proj_heads_kernel<<<gproj, 256>>>(k, wk, bk, 1);
    proj_heads_kernel<<<gproj, 256>>>(v, wv, bv, 2);

    dim3 gattn(Sc / 64, BH);                   // (32, 32)
    attn_logits_kernel<<<gattn, 256>>>(attn);
    attn_av_kernel<<<gattn, 256>>>(attn);

    out_proj_kernel<<<dim3(DM / 64, MROWS / 128), 256>>>(wo, bo, out);
}

// round 2
// speedup vs baseline: 1.0627x; 1.0627x over previous
#include <cuda_runtime.h>

// ---------------------------------------------------------------------------
// MultiHeadAttention: B=2, S=2048, D_MODEL=1024, H=16, DEPTH=64
// d_out = [ out (B,S,D) | attn (B,H,S,S) ]
// ---------------------------------------------------------------------------

namespace {
constexpr int Bc = 2;
constexpr int Sc = 2048;
constexpr int DM = 1024;
constexpr int Hc = 16;
constexpr int DEPTH = 64;
constexpr int BH = Bc * Hc;        // 32
constexpr int MROWS = Bc * Sc;     // 4096
constexpr float SCALE = 0.125f;    // 1/sqrt(64)
constexpr float NEG_BIG = -3.0e38f;
}

__device__ float g_qh[BH * Sc * DEPTH];   // (B,H,S,64)
__device__ float g_kh[BH * Sc * DEPTH];
__device__ float g_vh[BH * Sc * DEPTH];
__device__ float g_ctx[MROWS * DM];       // context, merged-head row-major
__device__ float g_m[BH * Sc];
__device__ float g_s[BH * Sc];

__device__ __forceinline__ float rmax16(float v) {
#pragma unroll
    for (int o = 8; o > 0; o >>= 1)
        v = fmaxf(v, __shfl_xor_sync(0xffffffffu, v, o));
    return v;
}
__device__ __forceinline__ float rsum16(float v) {
#pragma unroll
    for (int o = 8; o > 0; o >>= 1)
        v += __shfl_xor_sync(0xffffffffu, v, o);
    return v;
}

// ---------------------------------------------------------------------------
// Fused QKV projection. Tile 128(M) x 64(N) x 16(K), 256 thr, 8x4/thread.
// blockIdx.z selects q/k/v. Output written head-split.
// ---------------------------------------------------------------------------
__global__ __launch_bounds__(256) void qkv_proj_kernel(
    const float* __restrict__ q, const float* __restrict__ k,
    const float* __restrict__ v,
    const float* __restrict__ wq, const float* __restrict__ wk,
    const float* __restrict__ wv,
    const float* __restrict__ bq, const float* __restrict__ bk,
    const float* __restrict__ bv) {
    const int sel = blockIdx.z;
    const float* X = (sel == 0) ? q : ((sel == 1) ? k : v);
    const float* W = (sel == 0) ? wq : ((sel == 1) ? wk : wv);
    const float* bias = (sel == 0) ? bq : ((sel == 1) ? bk : bv);
    float* out = (sel == 0) ? g_qh : ((sel == 1) ? g_kh : g_vh);

    __shared__ float As[128][20];   // [m][k], pad 4 (80B rows, 16B aligned)
    __shared__ float Bs[16][68];    // [k][n], pad 4

    const int tid = threadIdx.x;
    const int tx = tid & 15;        // 4 cols each
    const int ty = tid >> 4;        // 8 rows each
    const int m0 = blockIdx.y * 128;
    const int n0 = blockIdx.x * 64;

    float acc[8][4];
#pragma unroll
    for (int i = 0; i < 8; i++)
#pragma unroll
        for (int j = 0; j < 4; j++) acc[i][j] = 0.0f;

    for (int k0 = 0; k0 < DM; k0 += 16) {
#pragma unroll
        for (int i = 0; i < 2; i++) {
            int e = tid + i * 256;
            int r = e >> 2, c4 = e & 3;
            float4 f = *(const float4*)&X[(size_t)(m0 + r) * DM + k0 + c4 * 4];
            *(float4*)&As[r][c4 * 4] = f;
        }
        {
            int r = tid >> 4, c4 = tid & 15;
            float4 f = *(const float4*)&W[(size_t)(k0 + r) * DM + n0 + c4 * 4];
            *(float4*)&Bs[r][c4 * 4] = f;
        }
        __syncthreads();
#pragma unroll
        for (int kk = 0; kk < 16; kk++) {
            float a[8];
#pragma unroll
            for (int i = 0; i < 8; i++) a[i] = As[ty * 8 + i][kk];
            float4 bv4 = *(const float4*)&Bs[kk][tx * 4];
#pragma unroll
            for (int i = 0; i < 8; i++) {
                acc[i][0] = fmaf(a[i], bv4.x, acc[i][0]);
                acc[i][1] = fmaf(a[i], bv4.y, acc[i][1]);
                acc[i][2] = fmaf(a[i], bv4.z, acc[i][2]);
                acc[i][3] = fmaf(a[i], bv4.w, acc[i][3]);
            }
        }
        __syncthreads();
    }

    const int h = n0 >> 6;                 // n0 is a multiple of 64
    float4 bb = *(const float4*)&bias[n0 + tx * 4];
#pragma unroll
    for (int i = 0; i < 8; i++) {
        int row = m0 + ty * 8 + i;
        int b = row >> 11, s = row & 2047;
        float4 o;
        o.x = acc[i][0] + bb.x;
        o.y = acc[i][1] + bb.y;
        o.z = acc[i][2] + bb.z;
        o.w = acc[i][3] + bb.w;
        *(float4*)&out[(((size_t)(b * Hc + h)) * Sc + s) * DEPTH + tx * 4] = o;
    }
}

// ---------------------------------------------------------------------------
// Pass 1: raw scaled logits -> attn region, online (max, sumexp) per row.
// Block: 128 q-rows x all k (16 tiles of 128). 8x8 per thread.
// ---------------------------------------------------------------------------
__global__ __launch_bounds__(256, 2) void logits_kernel(float* __restrict__ attn) {
    extern __shared__ float sm[];
    float (*Qs)[68] = (float(*)[68])sm;                 // 128 x 68 (q-major)
    float (*Kt)[132] = (float(*)[132])(sm + 128 * 68);  // 64 x 132 (d-major)

    const int bh = blockIdx.y;
    const int q0 = blockIdx.x * 128;
    const int tid = threadIdx.x;
    const int tx = tid & 15;    // 8 k-cols each
    const int ty = tid >> 4;    // 8 q-rows each

    const float* Qb = g_qh + (size_t)bh * Sc * DEPTH;
    const float* Kb = g_kh + (size_t)bh * Sc * DEPTH;

    // load Q tile (128 x 64), natural layout
#pragma unroll
    for (int i = 0; i < 8; i++) {
        int e = tid + i * 256;
        int r = e >> 4, c4 = e & 15;
        float4 f = *(const float4*)&Qb[(size_t)(q0 + r) * DEPTH + c4 * 4];
        *(float4*)&Qs[r][c4 * 4] = f;
    }

    float m_run[8], s_run[8];
#pragma unroll
    for (int i = 0; i < 8; i++) { m_run[i] = NEG_BIG; s_run[i] = 0.0f; }

    for (int k0 = 0; k0 < Sc; k0 += 128) {
        __syncthreads();
        // load K tile (128 k x 64 d) transposed -> Kt[d][k]
#pragma unroll
        for (int i = 0; i < 8; i++) {
            int e = tid + i * 256;
            int r = e >> 4, c4 = e & 15;
            float4 f = *(const float4*)&Kb[(size_t)(k0 + r) * DEPTH + c4 * 4];
            Kt[c4 * 4 + 0][r] = f.x;
            Kt[c4 * 4 + 1][r] = f.y;
            Kt[c4 * 4 + 2][r] = f.z;
            Kt[c4 * 4 + 3][r] = f.w;
        }
        __syncthreads();

        float l[8][8];
#pragma unroll
        for (int i = 0; i < 8; i++)
#pragma unroll
            for (int j = 0; j < 8; j++) l[i][j] = 0.0f;

#pragma unroll 16
        for (int d = 0; d < 64; d++) {
            float a[8];
#pragma unroll
            for (int i = 0; i < 8; i++) a[i] = Qs[ty * 8 + i][d];
            float4 b0 = *(const float4*)&Kt[d][tx * 8];
            float4 b1 = *(const float4*)&Kt[d][tx * 8 + 4];
#pragma unroll
            for (int i = 0; i < 8; i++) {
                l[i][0] = fmaf(a[i], b0.x, l[i][0]);
                l[i][1] = fmaf(a[i], b0.y, l[i][1]);
                l[i][2] = fmaf(a[i], b0.z, l[i][2]);
                l[i][3] = fmaf(a[i], b0.w, l[i][3]);
                l[i][4] = fmaf(a[i], b1.x, l[i][4]);
                l[i][5] = fmaf(a[i], b1.y, l[i][5]);
                l[i][6] = fmaf(a[i], b1.z, l[i][6]);
                l[i][7] = fmaf(a[i], b1.w, l[i][7]);
            }
        }

#pragma unroll
        for (int i = 0; i < 8; i++) {
            int row = q0 + ty * 8 + i;
            float* arow = attn + ((size_t)bh * Sc + row) * Sc + k0 + tx * 8;
            float tmax = NEG_BIG;
#pragma unroll
            for (int j = 0; j < 8; j++) {
                l[i][j] *= SCALE;
                tmax = fmaxf(tmax, l[i][j]);
            }
            float4 s0 = make_float4(l[i][0], l[i][1], l[i][2], l[i][3]);
            float4 s1 = make_float4(l[i][4], l[i][5], l[i][6], l[i][7]);
            *(float4*)&arow[0] = s0;
            *(float4*)&arow[4] = s1;
            tmax = rmax16(tmax);
            float mnew = fmaxf(m_run[i], tmax);
            float ps = 0.0f;
#pragma unroll
            for (int j = 0; j < 8; j++) ps += __expf(l[i][j] - mnew);
            ps = rsum16(ps);
            s_run[i] = s_run[i] * __expf(m_run[i] - mnew) + ps;
            m_run[i] = mnew;
        }
    }

    if (tx == 0) {
#pragma unroll
        for (int i = 0; i < 8; i++) {
            int row = q0 + ty * 8 + i;
            g_m[bh * Sc + row] = m_run[i];
            g_s[bh * Sc + row] = s_run[i];
        }
    }
}

// ---------------------------------------------------------------------------
// Pass 2: normalize attn in place + ctx = attn @ V (merged-head layout).
// Block: 128 q-rows x 64 d, k in chunks of 64. 4x8 per thread.
// ---------------------------------------------------------------------------
__global__ __launch_bounds__(256) void av_kernel(float* __restrict__ attn) {
    extern __shared__ float sm[];
    float (*Ps)[68] = (float(*)[68])sm;                // 128 x 68
    float (*Vs)[68] = (float(*)[68])(sm + 128 * 68);   // 64 x 68
    float* msm = sm + 128 * 68 + 64 * 68;              // 128
    float* ssm = msm + 128;                            // 128 (1/sum)

    const int bh = blockIdx.y;
    const int q0 = blockIdx.x * 128;
    const int tid = threadIdx.x;
    const int tx = tid & 7;     // 8 d-cols each
    const int ty = tid >> 3;    // 4 q-rows each

    const float* Vb = g_vh + (size_t)bh * Sc * DEPTH;

    if (tid < 128) {
        msm[tid] = g_m[bh * Sc + q0 + tid];
        ssm[tid] = 1.0f / g_s[bh * Sc + q0 + tid];
    }

    float acc[4][8];
#pragma unroll
    for (int i = 0; i < 4; i++)
#pragma unroll
        for (int j = 0; j < 8; j++) acc[i][j] = 0.0f;

    for (int k0 = 0; k0 < Sc; k0 += 64) {
        __syncthreads();
        // V tile 64 x 64
#pragma unroll
        for (int i = 0; i < 4; i++) {
            int e = tid + i * 256;
            int r = e >> 4, c4 = e & 15;
            float4 f = *(const float4*)&Vb[(size_t)(k0 + r) * DEPTH + c4 * 4];
            *(float4*)&Vs[r][c4 * 4] = f;
        }
        // P chunk 128 q x 64 k: read raw logits, exp-normalize, write back + smem
#pragma unroll
        for (int i = 0; i < 8; i++) {
            int e = tid + i * 256;
            int r = e >> 4, c4 = e & 15;
            float* gp = attn + ((size_t)bh * Sc + q0 + r) * Sc + k0 + c4 * 4;
            float4 x = *(const float4*)gp;
            float mm = msm[r], si = ssm[r];
            float4 p;
            p.x = __expf(x.x - mm) * si;
            p.y = __expf(x.y - mm) * si;
            p.z = __expf(x.z - mm) * si;
            p.w = __expf(x.w - mm) * si;
            *(float4*)gp = p;
            *(float4*)&Ps[r][c4 * 4] = p;
        }
        __syncthreads();

#pragma unroll 16
        for (int kk = 0; kk < 64; kk++) {
            float a[4];
#pragma unroll
            for (int i = 0; i < 4; i++) a[i] = Ps[ty * 4 + i][kk];
            float4 b0 = *(const float4*)&Vs[kk][tx * 8];
            float4 b1 = *(const float4*)&Vs[kk][tx * 8 + 4];
#pragma unroll
            for (int i = 0; i < 4; i++) {
                acc[i][0] = fmaf(a[i], b0.x, acc[i][0]);
                acc[i][1] = fmaf(a[i], b0.y, acc[i][1]);
                acc[i][2] = fmaf(a[i], b0.z, acc[i][2]);
                acc[i][3] = fmaf(a[i], b0.w, acc[i][3]);
                acc[i][4] = fmaf(a[i], b1.x, acc[i][4]);
                acc[i][5] = fmaf(a[i], b1.y, acc[i][5]);
                acc[i][6] = fmaf(a[i], b1.z, acc[i][6]);
                acc[i][7] = fmaf(a[i], b1.w, acc[i][7]);
            }
        }
    }

    // store ctx in merged layout: [(b*S+s)*DM + h*64 + d]
    const int b = bh >> 4, h = bh & 15;
#pragma unroll
    for (int i = 0; i < 4; i++) {
        int s = q0 + ty * 4 + i;
        float* cp = g_ctx + ((size_t)(b * Sc + s)) * DM + h * 64 + tx * 8;
        *(float4*)&cp[0] = make_float4(acc[i][0], acc[i][1], acc[i][2], acc[i][3]);
        *(float4*)&cp[4] = make_float4(acc[i][4], acc[i][5], acc[i][6], acc[i][7]);
    }
}

// ---------------------------------------------------------------------------
// Output projection: out = ctx @ wo + bo. Tile 128x64x16, 8x4/thread.
// ---------------------------------------------------------------------------
__global__ __launch_bounds__(256) void out_proj_kernel(
    const float* __restrict__ WO, const float* __restrict__ bo,
    float* __restrict__ out) {
    __shared__ float As[128][20];
    __shared__ float Bs[16][68];

    const int tid = threadIdx.x;
    const int tx = tid & 15;
    const int ty = tid >> 4;
    const int m0 = blockIdx.y * 128;
    const int n0 = blockIdx.x * 64;

    float acc[8][4];
#pragma unroll
    for (int i = 0; i < 8; i++)
#pragma unroll
        for (int j = 0; j < 4; j++) acc[i][j] = 0.0f;

    for (int k0 = 0; k0 < DM; k0 += 16) {
#pragma unroll
        for (int i = 0; i < 2; i++) {
            int e = tid + i * 256;
            int r = e >> 2, c4 = e & 3;
            float4 f = *(const float4*)&g_ctx[(size_t)(m0 + r) * DM + k0 + c4 * 4];
            *(float4*)&As[r][c4 * 4] = f;
        }
        {
            int r = tid >> 4, c4 = tid & 15;
            float4 f = *(const float4*)&WO[(size_t)(k0 + r) * DM + n0 + c4 * 4];
            *(float4*)&Bs[r][c4 * 4] = f;
        }
        __syncthreads();
#pragma unroll
        for (int kk = 0; kk < 16; kk++) {
            float a[8];
#pragma unroll
            for (int i = 0; i < 8; i++) a[i] = As[ty * 8 + i][kk];
            float4 bv4 = *(const float4*)&Bs[kk][tx * 4];
#pragma unroll
            for (int i = 0; i < 8; i++) {
                acc[i][0] = fmaf(a[i], bv4.x, acc[i][0]);
                acc[i][1] = fmaf(a[i], bv4.y, acc[i][1]);
                acc[i][2] = fmaf(a[i], bv4.z, acc[i][2]);
                acc[i][3] = fmaf(a[i], bv4.w, acc[i][3]);
            }
        }
        __syncthreads();
    }

    float4 bb = *(const float4*)&bo[n0 + tx * 4];
#pragma unroll
    for (int i = 0; i < 8; i++) {
        int row = m0 + ty * 8 + i;
        float4 o;
        o.x = acc[i][0] + bb.x;
        o.y = acc[i][1] + bb.y;
        o.z = acc[i][2] + bb.z;
        o.w = acc[i][3] + bb.w;
        *(float4*)&out[(size_t)row * DM + n0 + tx * 4] = o;
    }
}

// ---------------------------------------------------------------------------
extern "C" void kernel_launch(void* const* d_in, const int* in_sizes, int n_in,
                              void* d_out, int out_size) {
    const float* v  = (const float*)d_in[0];
    const float* k  = (const float*)d_in[1];
    const float* q  = (const float*)d_in[2];
    const float* wq = (const float*)d_in[3];
    const float* bq = (const float*)d_in[4];
    const float* wk = (const float*)d_in[5];
    const float* bk = (const float*)d_in[6];
    const float* wv = (const float*)d_in[7];
    const float* bv = (const float*)d_in[8];
    const float* wo = (const float*)d_in[9];
    const float* bo = (const float*)d_in[10];

    float* out  = (float*)d_out;
    float* attn = out + (size_t)MROWS * DM;

    const int logits_smem = (128 * 68 + 64 * 132) * 4;           // 68608
    const int av_smem     = (128 * 68 + 64 * 68 + 256) * 4;      // 53248
    cudaFuncSetAttribute(logits_kernel,
                         cudaFuncAttributeMaxDynamicSharedMemorySize, logits_smem);
    cudaFuncSetAttribute(av_kernel,
                         cudaFuncAttributeMaxDynamicSharedMemorySize, av_smem);

    qkv_proj_kernel<<<dim3(DM / 64, MROWS / 128, 3), 256>>>(
        q, k, v, wq, wk, wv, bq, bk, bv);

    logits_kernel<<<dim3(Sc / 128, BH), 256, logits_smem>>>(attn);
    av_kernel<<<dim3(Sc / 128, BH), 256, av_smem>>>(attn);

    out_proj_kernel<<<dim3(DM / 64, MROWS / 128), 256>>>(wo, bo, out);
}